// round 3
// baseline (speedup 1.0000x reference)
#include <cuda_runtime.h>
#include <cstdint>

#define SLEN 1024
#define BSZ  16
#define IND  256
#define NH   8
#define DH   32
#define PROJ 776              // NH*(3*DH+1)
#define NTOK (SLEN*BSZ)       // 16384
#define NCHAIN (BSZ*NH)       // 128
#define FW_ELEMS (NCHAIN*DH*DH)

// Scratch (static device globals; no runtime allocation)
__device__ float g_normed[(size_t)NTOK*IND];
__device__ float g_qkvb[(size_t)NTOK*PROJ];
__device__ float g_oseq[(size_t)NTOK*IND];

// ---------------------------------------------------------------------------
// Packed f32x2 helpers (Blackwell)
// ---------------------------------------------------------------------------
typedef unsigned long long u64t;

__device__ __forceinline__ u64t f2pack(float lo, float hi) {
    u64t r;
    asm("mov.b64 %0, {%1, %2};" : "=l"(r) : "f"(lo), "f"(hi));
    return r;
}
__device__ __forceinline__ void f2unpack(u64t v, float& lo, float& hi) {
    asm("mov.b64 {%0, %1}, %2;" : "=f"(lo), "=f"(hi) : "l"(v));
}
__device__ __forceinline__ u64t ffma2(u64t a, u64t b, u64t c) {
    u64t d;
    asm("fma.rn.f32x2 %0, %1, %2, %3;" : "=l"(d) : "l"(a), "l"(b), "l"(c));
    return d;
}

// ---------------------------------------------------------------------------
// LayerNorm: one block (256 threads) per token row
// ---------------------------------------------------------------------------
__global__ void ln_kernel(const float* __restrict__ x,
                          const float* __restrict__ gamma,
                          const float* __restrict__ beta)
{
    int row = blockIdx.x;
    int tid = threadIdx.x;
    float v = x[(size_t)row * IND + tid];
    float s = v, s2 = v * v;
#pragma unroll
    for (int o = 16; o > 0; o >>= 1) {
        s  += __shfl_xor_sync(0xffffffffu, s,  o);
        s2 += __shfl_xor_sync(0xffffffffu, s2, o);
    }
    __shared__ float sh[2][8];
    int w = tid >> 5, l = tid & 31;
    if (l == 0) { sh[0][w] = s; sh[1][w] = s2; }
    __syncthreads();
    float ts = 0.f, ts2 = 0.f;
#pragma unroll
    for (int i = 0; i < 8; i++) { ts += sh[0][i]; ts2 += sh[1][i]; }
    float mu  = ts * (1.0f / IND);
    float var = ts2 * (1.0f / IND) - mu * mu;
    float r   = rsqrtf(var + 1e-5f);
    g_normed[(size_t)row * IND + tid] = (v - mu) * r * gamma[tid] + beta[tid];
}

// ---------------------------------------------------------------------------
// Tiled NT GEMM: C[M,N] = A[M,K] * B[N,K]^T (+ resid), fp32, packed f32x2 FMA
// Block tile 128x128, BK=16, 256 threads, 8x8 microtile
// ---------------------------------------------------------------------------
#define BM 128
#define BN 128
#define BK 16
#define LDS_PAD 132   // floats per smem row; 132*4=528 bytes, 16B-aligned rows

__global__ __launch_bounds__(256, 2)
void gemm_nt(const float* __restrict__ A, const float* __restrict__ B,
             float* __restrict__ C, int M, int N, int K,
             const float* __restrict__ resid)
{
    __shared__ __align__(16) float As[BK][LDS_PAD];
    __shared__ __align__(16) float Bs[BK][LDS_PAD];

    int bm = blockIdx.x * BM;
    int bn = blockIdx.y * BN;
    int tid = threadIdx.x;
    int tx = tid & 15, ty = tid >> 4;     // tx: n dim, ty: m dim
    int m0 = ty * 8, n0 = tx * 8;

    u64t acc[8][4];
#pragma unroll
    for (int i = 0; i < 8; i++)
#pragma unroll
        for (int j = 0; j < 4; j++) acc[i][j] = 0ull;

    for (int k0 = 0; k0 < K; k0 += BK) {
        // cooperative load + transpose into smem (K-outer layout)
#pragma unroll
        for (int i = 0; i < 2; i++) {
            int f = tid + i * 256;            // float4 index 0..511
            int r = f >> 2;                   // row within tile (m or n), 0..127
            int kq = (f & 3) * 4;             // k offset 0,4,8,12
            float4 va = *(const float4*)(A + (size_t)(bm + r) * K + k0 + kq);
            As[kq + 0][r] = va.x; As[kq + 1][r] = va.y;
            As[kq + 2][r] = va.z; As[kq + 3][r] = va.w;
            float4 vb = make_float4(0.f, 0.f, 0.f, 0.f);
            if (bn + r < N)
                vb = *(const float4*)(B + (size_t)(bn + r) * K + k0 + kq);
            Bs[kq + 0][r] = vb.x; Bs[kq + 1][r] = vb.y;
            Bs[kq + 2][r] = vb.z; Bs[kq + 3][r] = vb.w;
        }
        __syncthreads();

#pragma unroll
        for (int kk = 0; kk < BK; kk++) {
            float4 a0 = *(const float4*)&As[kk][m0];
            float4 a1 = *(const float4*)&As[kk][m0 + 4];
            const u64t* bp = (const u64t*)&Bs[kk][n0];
            u64t b0 = bp[0], b1 = bp[1], b2 = bp[2], b3 = bp[3];

            u64t as[8];
            as[0] = f2pack(a0.x, a0.x); as[1] = f2pack(a0.y, a0.y);
            as[2] = f2pack(a0.z, a0.z); as[3] = f2pack(a0.w, a0.w);
            as[4] = f2pack(a1.x, a1.x); as[5] = f2pack(a1.y, a1.y);
            as[6] = f2pack(a1.z, a1.z); as[7] = f2pack(a1.w, a1.w);
#pragma unroll
            for (int i = 0; i < 8; i++) {
                acc[i][0] = ffma2(as[i], b0, acc[i][0]);
                acc[i][1] = ffma2(as[i], b1, acc[i][1]);
                acc[i][2] = ffma2(as[i], b2, acc[i][2]);
                acc[i][3] = ffma2(as[i], b3, acc[i][3]);
            }
        }
        __syncthreads();
    }

#pragma unroll
    for (int i = 0; i < 8; i++) {
        int m = bm + m0 + i;
#pragma unroll
        for (int j = 0; j < 4; j++) {
            float c0, c1;
            f2unpack(acc[i][j], c0, c1);
            int n = bn + n0 + 2 * j;
            if (n < N) {
                float v0 = c0;
                if (resid) v0 += resid[(size_t)m * N + n];
                C[(size_t)m * N + n] = v0;
            }
            if (n + 1 < N) {
                float v1 = c1;
                if (resid) v1 += resid[(size_t)m * N + n + 1];
                C[(size_t)m * N + n + 1] = v1;
            }
        }
    }
}

// ---------------------------------------------------------------------------
// Delta-rule recurrence: one warp per (batch, head) chain.
// Thread `lane` owns row `lane` of the 32x32 fast-weight matrix (packed f32x2).
// Normalization is folded AFTER the matvec so the shuffle reduction and the
// matvec run concurrently:
//   v_old = (W . ek) / s_k,  k.q = (sum eq*ek)/(s_q*s_k)
//   delta = beta*(v - v_old); o = W.q/s_q + delta*(k.q); W += (delta/s_k) ek^T
// ---------------------------------------------------------------------------
__global__ __launch_bounds__(32)
void rec_kernel(const float* __restrict__ state,
                float* __restrict__ out_fw, int write_fw)
{
    int chain = blockIdx.x;            // 0..127
    int b = chain >> 3, h = chain & 7;
    int lane = threadIdx.x;

    // W row `lane` as 16 packed pairs (memory layout matches little-endian pack)
    u64t Wp[16];
    const u64t* st = (const u64t*)(state + ((size_t)chain * DH + lane) * DH);
#pragma unroll
    for (int j = 0; j < 16; j++) Wp[j] = st[j];

    __shared__ __align__(16) float sek[2][DH];
    __shared__ __align__(16) float seq_[2][DH];

    const float* base = g_qkvb + (size_t)b * PROJ + (size_t)h * 97;

    // prefetch t = 0
    float qc = base[lane], kc = base[32 + lane], vc = base[64 + lane], bc = base[96];

    for (int t = 0; t < SLEN; t++) {
        // prefetch t+1 (hidden under this step's compute)
        float qn = 0.f, kn = 0.f, vn = 0.f, bn2 = 0.f;
        if (t + 1 < SLEN) {
            const float* nxt = base + (size_t)(t + 1) * BSZ * PROJ;
            qn = nxt[lane]; kn = nxt[32 + lane]; vn = nxt[64 + lane]; bn2 = nxt[96];
        }

        // elu(x)+1 (un-normalized)
        float eq = qc > 0.f ? qc + 1.f : __expf(qc);
        float ek = kc > 0.f ? kc + 1.f : __expf(kc);

        int bufi = t & 1;
        sek[bufi][lane]  = ek;
        seq_[bufi][lane] = eq;

        // fused 3-way reduction: s_q, s_k, sum(eq*ek) — one 5-level chain
        float sq = eq, sk = ek, sqk = eq * ek;
#pragma unroll
        for (int o = 16; o > 0; o >>= 1) {
            sq  += __shfl_xor_sync(0xffffffffu, sq,  o);
            sk  += __shfl_xor_sync(0xffffffffu, sk,  o);
            sqk += __shfl_xor_sync(0xffffffffu, sqk, o);
        }
        __syncwarp();

        // matvecs on raw ek/eq (packed f32x2), overlapping reduction latency
        u64t kr[16];
        u64t ak0 = 0ull, ak1 = 0ull, aq0 = 0ull, aq1 = 0ull;
        const ulonglong2* kp = (const ulonglong2*)sek[bufi];
        const ulonglong2* qp = (const ulonglong2*)seq_[bufi];
#pragma unroll
        for (int j = 0; j < 8; j++) {
            ulonglong2 k2 = kp[j];
            ulonglong2 q2 = qp[j];
            kr[2 * j]     = k2.x;
            kr[2 * j + 1] = k2.y;
            ak0 = ffma2(Wp[2 * j],     k2.x, ak0);
            ak1 = ffma2(Wp[2 * j + 1], k2.y, ak1);
            aq0 = ffma2(Wp[2 * j],     q2.x, aq0);
            aq1 = ffma2(Wp[2 * j + 1], q2.y, aq1);
        }
        float x0, x1, y0, y1;
        f2unpack(ak0, x0, x1); f2unpack(ak1, y0, y1);
        float v_raw = (x0 + y0) + (x1 + y1);
        f2unpack(aq0, x0, x1); f2unpack(aq1, y0, y1);
        float w_raw = (x0 + y0) + (x1 + y1);

        float rsk = 1.0f / (sk + 1e-5f);
        float rsq = 1.0f / (sq + 1e-5f);
        float beta = 1.0f / (1.0f + __expf(-bc));

        float v_old = v_raw * rsk;
        float wq    = w_raw * rsq;
        float kqdot = sqk * rsk * rsq;
        float delta = beta * (vc - v_old);
        float o_out = fmaf(delta, kqdot, wq);

        g_oseq[((size_t)t * BSZ + b) * IND + h * DH + lane] = o_out;

        // W += (delta*rsk) * ek^T   (normalization folded into scalar)
        float dk = delta * rsk;
        u64t dd = f2pack(dk, dk);
#pragma unroll
        for (int j = 0; j < 16; j++) Wp[j] = ffma2(dd, kr[j], Wp[j]);

        qc = qn; kc = kn; vc = vn; bc = bn2;
    }

    if (write_fw) {
        u64t* fw = (u64t*)(out_fw + ((size_t)chain * DH + lane) * DH);
#pragma unroll
        for (int j = 0; j < 16; j++) fw[j] = Wp[j];
    }
}

// ---------------------------------------------------------------------------
extern "C" void kernel_launch(void* const* d_in, const int* in_sizes, int n_in,
                              void* d_out, int out_size)
{
    const float* x        = (const float*)d_in[0];
    const float* state    = (const float*)d_in[1];
    const float* W_slow   = (const float*)d_in[2];
    const float* ln_gamma = (const float*)d_in[3];
    const float* ln_beta  = (const float*)d_in[4];
    const float* W_out    = (const float*)d_in[5];
    float* out = (float*)d_out;

    float* normed; cudaGetSymbolAddress((void**)&normed, g_normed);
    float* qkvb;   cudaGetSymbolAddress((void**)&qkvb,   g_qkvb);
    float* oseq;   cudaGetSymbolAddress((void**)&oseq,   g_oseq);

    // 1) LayerNorm
    ln_kernel<<<NTOK, IND>>>(x, ln_gamma, ln_beta);

    // 2) qkvb = normed @ W_slow^T   [16384 x 776]
    dim3 gB(NTOK / BM, (PROJ + BN - 1) / BN);
    gemm_nt<<<gB, 256>>>(normed, W_slow, qkvb, NTOK, PROJ, IND, nullptr);

    // 3) delta-rule recurrence (writes g_oseq and final fast weights)
    int write_fw = (out_size >= (int)((size_t)NTOK * IND + FW_ELEMS)) ? 1 : 0;
    rec_kernel<<<NCHAIN, DH>>>(state, out + (size_t)NTOK * IND, write_fw);

    // 4) out = x + oseq @ W_out^T   [16384 x 256]
    dim3 gD(NTOK / BM, (IND + BN - 1) / BN);
    gemm_nt<<<gD, 256>>>(oseq, W_out, out, NTOK, IND, IND, x);
}